// round 1
// baseline (speedup 1.0000x reference)
#include <cuda_runtime.h>
#include <math.h>

#define DIN   256
#define DMID  512
#define NTAP  9
#define ATOT  150111           // 3 * sum(H*W) over 5 levels
#define NB    4

// Transposed conv weights: [c][tap][o]  (contiguous per 4-input-channel chunk)
__device__ float g_wt[DIN * NTAP * DMID];

__global__ void prep_weights(const float* __restrict__ Wc) {
    int idx = blockIdx.x * blockDim.x + threadIdx.x;
    if (idx >= DIN * NTAP * DMID) return;
    int o  = idx % DMID;
    int ct = idx / DMID;           // c*9 + tap
    int c  = ct / NTAP;
    int t  = ct % NTAP;
    g_wt[idx] = Wc[(o * DIN + c) * NTAP + t];
}

// SMEM layout (dynamic):
//  [0 .. 76032):  mainloop: s_w  [4][9][512] f32 (73728 B)
//                 epilogue: s_p  [18][512]   (36864 B)  +  s_red [32][18][17] (39168 B)
//  [76032 .. 77760): s_x [4][3][36]
//  [77760 .. 80320): s_out [32][20]
#define SMEM_BYTES 80320

__global__ void __launch_bounds__(256)
rpn_level_kernel(const float* __restrict__ x,        // [4,256,H,W]
                 const float* __restrict__ b_conv,   // [512]
                 const float* __restrict__ W_cls,    // [6,512]
                 const float* __restrict__ b_cls,    // [6]
                 const float* __restrict__ W_box,    // [12,512]
                 const float* __restrict__ b_box,    // [12]
                 float* __restrict__ out,
                 int H, int W, int rowBase)
{
    extern __shared__ char sm[];
    float* s_w   = (float*)sm;
    float* s_p   = (float*)sm;
    float* s_red = (float*)(sm + 36864);
    float* s_x   = (float*)(sm + 76032);
    float* s_out = (float*)(sm + 77760);

    const int tid  = threadIdx.x;
    const int lane = tid & 31;
    const int warp = tid >> 5;
    // thread tile: 2 positions x 32 mid-channels
    const int pg = lane & 15;                  // positions 2pg, 2pg+1
    const int cg = (warp << 1) | (lane >> 4);  // 16 channel groups of 32
    const int o0 = cg * 32;
    const int p0 = pg * 2;

    const int w0 = blockIdx.x * 32;
    const int h  = blockIdx.y;
    const int b  = blockIdx.z;

    const float* xb = x + (size_t)b * DIN * H * W;

    float acc[2][32];
#pragma unroll
    for (int p = 0; p < 2; p++)
#pragma unroll
        for (int i = 0; i < 32; i++) acc[p][i] = 0.f;

    for (int c0 = 0; c0 < DIN; c0 += 4) {
        // stage weights: 18432 contiguous floats = 4608 float4
        {
            const float4* gw  = (const float4*)(g_wt + c0 * NTAP * DMID);
            float4*       sw4 = (float4*)s_w;
#pragma unroll
            for (int i = 0; i < 18; i++)
                sw4[tid + i * 256] = gw[tid + i * 256];
        }
        // stage input window: 4 ch x 3 rows x 34 cols (zero-padded borders)
        for (int i = tid; i < 4 * 3 * 34; i += 256) {
            int col = i % 34;
            int rr  = (i / 34) % 3;
            int cc  = i / (34 * 3);
            int gw_ = w0 - 1 + col;
            int gh  = h - 1 + rr;
            float v = 0.f;
            if (gw_ >= 0 && gw_ < W && gh >= 0 && gh < H)
                v = xb[((size_t)(c0 + cc) * H + gh) * W + gw_];
            s_x[(cc * 3 + rr) * 36 + col] = v;
        }
        __syncthreads();

#pragma unroll 2
        for (int kc = 0; kc < 4; kc++) {
#pragma unroll
            for (int ty = 0; ty < 3; ty++) {
                float xr[4];
#pragma unroll
                for (int q = 0; q < 4; q++)
                    xr[q] = s_x[(kc * 3 + ty) * 36 + p0 + q];
#pragma unroll
                for (int tx = 0; tx < 3; tx++) {
                    const float4* wv =
                        (const float4*)(s_w + ((kc * 9) + ty * 3 + tx) * DMID + o0);
#pragma unroll
                    for (int q = 0; q < 8; q++) {
                        float4 wq = wv[q];
#pragma unroll
                        for (int p = 0; p < 2; p++) {
                            float xv = xr[p + tx];
                            acc[p][4 * q + 0] += xv * wq.x;
                            acc[p][4 * q + 1] += xv * wq.y;
                            acc[p][4 * q + 2] += xv * wq.z;
                            acc[p][4 * q + 3] += xv * wq.w;
                        }
                    }
                }
            }
        }
        __syncthreads();
    }

    // bias + ReLU
#pragma unroll
    for (int i = 0; i < 32; i++) {
        float bc = b_conv[o0 + i];
#pragma unroll
        for (int p = 0; p < 2; p++) {
            float v = acc[p][i] + bc;
            acc[p][i] = v > 0.f ? v : 0.f;
        }
    }
    __syncthreads();   // retire s_w / s_x

    // stage projection weights: s_p[18][512] = [W_cls ; W_box]
    for (int i = tid; i < 6 * DMID; i += 256)  s_p[i] = W_cls[i];
    for (int i = tid; i < 12 * DMID; i += 256) s_p[6 * DMID + i] = W_box[i];
    __syncthreads();

    // per-thread partial projections -> s_red[pos][j][cg]
    for (int j = 0; j < 18; j++) {
        const float4* pr = (const float4*)(s_p + j * DMID + o0);
        float s0 = 0.f, s1 = 0.f;
#pragma unroll
        for (int q = 0; q < 8; q++) {
            float4 wq = pr[q];
            s0 += acc[0][4*q+0]*wq.x + acc[0][4*q+1]*wq.y + acc[0][4*q+2]*wq.z + acc[0][4*q+3]*wq.w;
            s1 += acc[1][4*q+0]*wq.x + acc[1][4*q+1]*wq.y + acc[1][4*q+2]*wq.z + acc[1][4*q+3]*wq.w;
        }
        s_red[((p0 + 0) * 18 + j) * 17 + cg] = s0;
        s_red[((p0 + 1) * 18 + j) * 17 + cg] = s1;
    }
    __syncthreads();

    // cross-thread reduce over 16 channel groups, add head bias
    for (int t2 = tid; t2 < 32 * 18; t2 += 256) {
        int pos = t2 / 18, j = t2 % 18;
        float s = 0.f;
#pragma unroll
        for (int g = 0; g < 16; g++) s += s_red[(pos * 18 + j) * 17 + g];
        s += (j < 6) ? b_cls[j] : b_box[j - 6];
        s_out[pos * 20 + j] = s;
    }
    __syncthreads();

    // write: score / prob(softmax over channel pairs (r, r+3)) / bbox
    if (tid < 96) {
        int pos = tid / 3, a = tid % 3;
        int w = w0 + pos;
        if (w < W) {
            int row   = rowBase + (h * W + w) * 3 + a;
            const float* so = s_out + pos * 20;
            int base2 = (b * ATOT + row) * 2;
            // score: channels (2a, 2a+1)
            out[base2 + 0] = so[2 * a + 0];
            out[base2 + 1] = so[2 * a + 1];
            // prob
            float* pout = out + (size_t)2 * NB * ATOT;
#pragma unroll
            for (int k = 0; k < 2; k++) {
                int c = 2 * a + k;
                int r = c % 3;
                float u = so[r], v = so[r + 3];
                float m  = fmaxf(u, v);
                float eu = __expf(u - m), ev = __expf(v - m);
                float num = (c < 3) ? eu : ev;
                pout[base2 + k] = num / (eu + ev);
            }
            // bbox: channels 4a..4a+3
            float* bout = out + (size_t)4 * NB * ATOT;
            int base4 = (b * ATOT + row) * 4;
#pragma unroll
            for (int j = 0; j < 4; j++) bout[base4 + j] = so[6 + 4 * a + j];
        }
    }
}

extern "C" void kernel_launch(void* const* d_in, const int* in_sizes, int n_in,
                              void* d_out, int out_size) {
    const float* feats[5];
    for (int i = 0; i < 5; i++) feats[i] = (const float*)d_in[i];
    // d_in[5] = im_info (unused by the reference computation)
    const float* W_conv = (const float*)d_in[6];
    const float* b_conv = (const float*)d_in[7];
    const float* W_cls  = (const float*)d_in[8];
    const float* b_cls  = (const float*)d_in[9];
    const float* W_box  = (const float*)d_in[10];
    const float* b_box  = (const float*)d_in[11];
    float* out = (float*)d_out;

    static const int HS[5] = {150, 75, 38, 19, 10};
    static const int WS[5] = {250, 125, 63, 32, 16};
    static const int RB[5] = {0, 112500, 140625, 147807, 149631};

    cudaFuncSetAttribute(rpn_level_kernel,
                         cudaFuncAttributeMaxDynamicSharedMemorySize, SMEM_BYTES);

    prep_weights<<<(DIN * NTAP * DMID + 255) / 256, 256>>>(W_conv);

    for (int l = 0; l < 5; l++) {
        dim3 grid((WS[l] + 31) / 32, HS[l], NB);
        rpn_level_kernel<<<grid, 256, SMEM_BYTES>>>(
            feats[l], b_conv, W_cls, b_cls, W_box, b_box, out,
            HS[l], WS[l], RB[l]);
    }
}

// round 2
// speedup vs baseline: 1.0005x; 1.0005x over previous
#include <cuda_runtime.h>
#include <math.h>

#define DIN   256
#define DMID  512
#define NTAP  9
#define ATOT  150111           // 3 * sum(H*W) over 5 levels
#define NB    4

// Transposed conv weights: [c][tap][o]  (contiguous per 4-input-channel chunk)
__device__ float g_wt[DIN * NTAP * DMID];

__global__ void prep_weights(const float* __restrict__ Wc) {
    int idx = blockIdx.x * blockDim.x + threadIdx.x;
    if (idx >= DIN * NTAP * DMID) return;
    int o  = idx % DMID;
    int ct = idx / DMID;           // c*9 + tap
    int c  = ct / NTAP;
    int t  = ct % NTAP;
    g_wt[idx] = Wc[(o * DIN + c) * NTAP + t];
}

// SMEM layout (dynamic):
//  [0 .. 76032):  mainloop: s_w  [4][9][512] f32 (73728 B)
//                 epilogue: s_p  [18][512]   (36864 B)  +  s_red [32][18][17] (39168 B)
//  [76032 .. 77760): s_x [4][3][36]
//  [77760 .. 80320): s_out [32][20]
#define SMEM_BYTES 80320

__global__ void __launch_bounds__(256)
rpn_level_kernel(const float* __restrict__ x,        // [4,256,H,W]
                 const float* __restrict__ b_conv,   // [512]
                 const float* __restrict__ W_cls,    // [6,512]
                 const float* __restrict__ b_cls,    // [6]
                 const float* __restrict__ W_box,    // [12,512]
                 const float* __restrict__ b_box,    // [12]
                 float* __restrict__ out,
                 int H, int W, int rowBase)
{
    extern __shared__ char sm[];
    float* s_w   = (float*)sm;
    float* s_p   = (float*)sm;
    float* s_red = (float*)(sm + 36864);
    float* s_x   = (float*)(sm + 76032);
    float* s_out = (float*)(sm + 77760);

    const int tid  = threadIdx.x;
    const int lane = tid & 31;
    const int warp = tid >> 5;
    // thread tile: 2 positions x 32 mid-channels
    const int pg = lane & 15;                  // positions 2pg, 2pg+1
    const int cg = (warp << 1) | (lane >> 4);  // 16 channel groups of 32
    const int o0 = cg * 32;
    const int p0 = pg * 2;

    const int w0 = blockIdx.x * 32;
    const int h  = blockIdx.y;
    const int b  = blockIdx.z;

    const float* xb = x + (size_t)b * DIN * H * W;

    float acc[2][32];
#pragma unroll
    for (int p = 0; p < 2; p++)
#pragma unroll
        for (int i = 0; i < 32; i++) acc[p][i] = 0.f;

    for (int c0 = 0; c0 < DIN; c0 += 4) {
        // stage weights: 18432 contiguous floats = 4608 float4
        {
            const float4* gw  = (const float4*)(g_wt + c0 * NTAP * DMID);
            float4*       sw4 = (float4*)s_w;
#pragma unroll
            for (int i = 0; i < 18; i++)
                sw4[tid + i * 256] = gw[tid + i * 256];
        }
        // stage input window: 4 ch x 3 rows x 34 cols (zero-padded borders)
        for (int i = tid; i < 4 * 3 * 34; i += 256) {
            int col = i % 34;
            int rr  = (i / 34) % 3;
            int cc  = i / (34 * 3);
            int gw_ = w0 - 1 + col;
            int gh  = h - 1 + rr;
            float v = 0.f;
            if (gw_ >= 0 && gw_ < W && gh >= 0 && gh < H)
                v = xb[((size_t)(c0 + cc) * H + gh) * W + gw_];
            s_x[(cc * 3 + rr) * 36 + col] = v;
        }
        __syncthreads();

#pragma unroll 2
        for (int kc = 0; kc < 4; kc++) {
#pragma unroll
            for (int ty = 0; ty < 3; ty++) {
                float xr[4];
#pragma unroll
                for (int q = 0; q < 4; q++)
                    xr[q] = s_x[(kc * 3 + ty) * 36 + p0 + q];
#pragma unroll
                for (int tx = 0; tx < 3; tx++) {
                    const float4* wv =
                        (const float4*)(s_w + ((kc * 9) + ty * 3 + tx) * DMID + o0);
#pragma unroll
                    for (int q = 0; q < 8; q++) {
                        float4 wq = wv[q];
#pragma unroll
                        for (int p = 0; p < 2; p++) {
                            float xv = xr[p + tx];
                            acc[p][4 * q + 0] += xv * wq.x;
                            acc[p][4 * q + 1] += xv * wq.y;
                            acc[p][4 * q + 2] += xv * wq.z;
                            acc[p][4 * q + 3] += xv * wq.w;
                        }
                    }
                }
            }
        }
        __syncthreads();
    }

    // bias + ReLU
#pragma unroll
    for (int i = 0; i < 32; i++) {
        float bc = b_conv[o0 + i];
#pragma unroll
        for (int p = 0; p < 2; p++) {
            float v = acc[p][i] + bc;
            acc[p][i] = v > 0.f ? v : 0.f;
        }
    }
    __syncthreads();   // retire s_w / s_x

    // stage projection weights: s_p[18][512] = [W_cls ; W_box]
    for (int i = tid; i < 6 * DMID; i += 256)  s_p[i] = W_cls[i];
    for (int i = tid; i < 12 * DMID; i += 256) s_p[6 * DMID + i] = W_box[i];
    __syncthreads();

    // per-thread partial projections -> s_red[pos][j][cg]
    for (int j = 0; j < 18; j++) {
        const float4* pr = (const float4*)(s_p + j * DMID + o0);
        float s0 = 0.f, s1 = 0.f;
#pragma unroll
        for (int q = 0; q < 8; q++) {
            float4 wq = pr[q];
            s0 += acc[0][4*q+0]*wq.x + acc[0][4*q+1]*wq.y + acc[0][4*q+2]*wq.z + acc[0][4*q+3]*wq.w;
            s1 += acc[1][4*q+0]*wq.x + acc[1][4*q+1]*wq.y + acc[1][4*q+2]*wq.z + acc[1][4*q+3]*wq.w;
        }
        s_red[((p0 + 0) * 18 + j) * 17 + cg] = s0;
        s_red[((p0 + 1) * 18 + j) * 17 + cg] = s1;
    }
    __syncthreads();

    // cross-thread reduce over 16 channel groups, add head bias
    for (int t2 = tid; t2 < 32 * 18; t2 += 256) {
        int pos = t2 / 18, j = t2 % 18;
        float s = 0.f;
#pragma unroll
        for (int g = 0; g < 16; g++) s += s_red[(pos * 18 + j) * 17 + g];
        s += (j < 6) ? b_cls[j] : b_box[j - 6];
        s_out[pos * 20 + j] = s;
    }
    __syncthreads();

    // write: score / prob(softmax over channel pairs (r, r+3)) / bbox
    if (tid < 96) {
        int pos = tid / 3, a = tid % 3;
        int w = w0 + pos;
        if (w < W) {
            int row   = rowBase + (h * W + w) * 3 + a;
            const float* so = s_out + pos * 20;
            int base2 = (b * ATOT + row) * 2;
            // score: channels (2a, 2a+1)
            out[base2 + 0] = so[2 * a + 0];
            out[base2 + 1] = so[2 * a + 1];
            // prob
            float* pout = out + (size_t)2 * NB * ATOT;
#pragma unroll
            for (int k = 0; k < 2; k++) {
                int c = 2 * a + k;
                int r = c % 3;
                float u = so[r], v = so[r + 3];
                float m  = fmaxf(u, v);
                float eu = __expf(u - m), ev = __expf(v - m);
                float num = (c < 3) ? eu : ev;
                pout[base2 + k] = num / (eu + ev);
            }
            // bbox: channels 4a..4a+3
            float* bout = out + (size_t)4 * NB * ATOT;
            int base4 = (b * ATOT + row) * 4;
#pragma unroll
            for (int j = 0; j < 4; j++) bout[base4 + j] = so[6 + 4 * a + j];
        }
    }
}

extern "C" void kernel_launch(void* const* d_in, const int* in_sizes, int n_in,
                              void* d_out, int out_size) {
    const float* feats[5];
    for (int i = 0; i < 5; i++) feats[i] = (const float*)d_in[i];
    // d_in[5] = im_info (unused by the reference computation)
    const float* W_conv = (const float*)d_in[6];
    const float* b_conv = (const float*)d_in[7];
    const float* W_cls  = (const float*)d_in[8];
    const float* b_cls  = (const float*)d_in[9];
    const float* W_box  = (const float*)d_in[10];
    const float* b_box  = (const float*)d_in[11];
    float* out = (float*)d_out;

    static const int HS[5] = {150, 75, 38, 19, 10};
    static const int WS[5] = {250, 125, 63, 32, 16};
    static const int RB[5] = {0, 112500, 140625, 147807, 149631};

    cudaFuncSetAttribute(rpn_level_kernel,
                         cudaFuncAttributeMaxDynamicSharedMemorySize, SMEM_BYTES);

    prep_weights<<<(DIN * NTAP * DMID + 255) / 256, 256>>>(W_conv);

    for (int l = 0; l < 5; l++) {
        dim3 grid((WS[l] + 31) / 32, HS[l], NB);
        rpn_level_kernel<<<grid, 256, SMEM_BYTES>>>(
            feats[l], b_conv, W_cls, b_cls, W_box, b_box, out,
            HS[l], WS[l], RB[l]);
    }
}

// round 3
// speedup vs baseline: 1.0008x; 1.0003x over previous
#include <cuda_runtime.h>
#include <math.h>

#define DIN   256
#define DMID  512
#define NTAP  9
#define ATOT  150111           // 3 * sum(H*W) over 5 levels
#define NB    4

// Transposed conv weights: [c][tap][o]  (contiguous per 4-input-channel chunk)
__device__ float g_wt[DIN * NTAP * DMID];

__global__ void prep_weights(const float* __restrict__ Wc) {
    int idx = blockIdx.x * blockDim.x + threadIdx.x;
    if (idx >= DIN * NTAP * DMID) return;
    int o  = idx % DMID;
    int ct = idx / DMID;           // c*9 + tap
    int c  = ct / NTAP;
    int t  = ct % NTAP;
    g_wt[idx] = Wc[(o * DIN + c) * NTAP + t];
}

// SMEM layout (dynamic):
//  [0 .. 76032):  mainloop: s_w  [4][9][512] f32 (73728 B)
//                 epilogue: s_p  [18][512]   (36864 B)  +  s_red [32][18][17] (39168 B)
//  [76032 .. 77760): s_x [4][3][36]
//  [77760 .. 80320): s_out [32][20]
#define SMEM_BYTES 80320

__global__ void __launch_bounds__(256)
rpn_level_kernel(const float* __restrict__ x,        // [4,256,H,W]
                 const float* __restrict__ b_conv,   // [512]
                 const float* __restrict__ W_cls,    // [6,512]
                 const float* __restrict__ b_cls,    // [6]
                 const float* __restrict__ W_box,    // [12,512]
                 const float* __restrict__ b_box,    // [12]
                 float* __restrict__ out,
                 int H, int W, int rowBase)
{
    extern __shared__ char sm[];
    float* s_w   = (float*)sm;
    float* s_p   = (float*)sm;
    float* s_red = (float*)(sm + 36864);
    float* s_x   = (float*)(sm + 76032);
    float* s_out = (float*)(sm + 77760);

    const int tid  = threadIdx.x;
    const int lane = tid & 31;
    const int warp = tid >> 5;
    // thread tile: 2 positions x 32 mid-channels
    const int pg = lane & 15;                  // positions 2pg, 2pg+1
    const int cg = (warp << 1) | (lane >> 4);  // 16 channel groups of 32
    const int o0 = cg * 32;
    const int p0 = pg * 2;

    const int w0 = blockIdx.x * 32;
    const int h  = blockIdx.y;
    const int b  = blockIdx.z;

    const float* xb = x + (size_t)b * DIN * H * W;

    float acc[2][32];
#pragma unroll
    for (int p = 0; p < 2; p++)
#pragma unroll
        for (int i = 0; i < 32; i++) acc[p][i] = 0.f;

    for (int c0 = 0; c0 < DIN; c0 += 4) {
        // stage weights: 18432 contiguous floats = 4608 float4
        {
            const float4* gw  = (const float4*)(g_wt + c0 * NTAP * DMID);
            float4*       sw4 = (float4*)s_w;
#pragma unroll
            for (int i = 0; i < 18; i++)
                sw4[tid + i * 256] = gw[tid + i * 256];
        }
        // stage input window: 4 ch x 3 rows x 34 cols (zero-padded borders)
        for (int i = tid; i < 4 * 3 * 34; i += 256) {
            int col = i % 34;
            int rr  = (i / 34) % 3;
            int cc  = i / (34 * 3);
            int gw_ = w0 - 1 + col;
            int gh  = h - 1 + rr;
            float v = 0.f;
            if (gw_ >= 0 && gw_ < W && gh >= 0 && gh < H)
                v = xb[((size_t)(c0 + cc) * H + gh) * W + gw_];
            s_x[(cc * 3 + rr) * 36 + col] = v;
        }
        __syncthreads();

#pragma unroll 2
        for (int kc = 0; kc < 4; kc++) {
#pragma unroll
            for (int ty = 0; ty < 3; ty++) {
                float xr[4];
#pragma unroll
                for (int q = 0; q < 4; q++)
                    xr[q] = s_x[(kc * 3 + ty) * 36 + p0 + q];
#pragma unroll
                for (int tx = 0; tx < 3; tx++) {
                    const float4* wv =
                        (const float4*)(s_w + ((kc * 9) + ty * 3 + tx) * DMID + o0);
#pragma unroll
                    for (int q = 0; q < 8; q++) {
                        float4 wq = wv[q];
#pragma unroll
                        for (int p = 0; p < 2; p++) {
                            float xv = xr[p + tx];
                            acc[p][4 * q + 0] += xv * wq.x;
                            acc[p][4 * q + 1] += xv * wq.y;
                            acc[p][4 * q + 2] += xv * wq.z;
                            acc[p][4 * q + 3] += xv * wq.w;
                        }
                    }
                }
            }
        }
        __syncthreads();
    }

    // bias + ReLU
#pragma unroll
    for (int i = 0; i < 32; i++) {
        float bc = b_conv[o0 + i];
#pragma unroll
        for (int p = 0; p < 2; p++) {
            float v = acc[p][i] + bc;
            acc[p][i] = v > 0.f ? v : 0.f;
        }
    }
    __syncthreads();   // retire s_w / s_x

    // stage projection weights: s_p[18][512] = [W_cls ; W_box]
    for (int i = tid; i < 6 * DMID; i += 256)  s_p[i] = W_cls[i];
    for (int i = tid; i < 12 * DMID; i += 256) s_p[6 * DMID + i] = W_box[i];
    __syncthreads();

    // per-thread partial projections -> s_red[pos][j][cg]
    for (int j = 0; j < 18; j++) {
        const float4* pr = (const float4*)(s_p + j * DMID + o0);
        float s0 = 0.f, s1 = 0.f;
#pragma unroll
        for (int q = 0; q < 8; q++) {
            float4 wq = pr[q];
            s0 += acc[0][4*q+0]*wq.x + acc[0][4*q+1]*wq.y + acc[0][4*q+2]*wq.z + acc[0][4*q+3]*wq.w;
            s1 += acc[1][4*q+0]*wq.x + acc[1][4*q+1]*wq.y + acc[1][4*q+2]*wq.z + acc[1][4*q+3]*wq.w;
        }
        s_red[((p0 + 0) * 18 + j) * 17 + cg] = s0;
        s_red[((p0 + 1) * 18 + j) * 17 + cg] = s1;
    }
    __syncthreads();

    // cross-thread reduce over 16 channel groups, add head bias
    for (int t2 = tid; t2 < 32 * 18; t2 += 256) {
        int pos = t2 / 18, j = t2 % 18;
        float s = 0.f;
#pragma unroll
        for (int g = 0; g < 16; g++) s += s_red[(pos * 18 + j) * 17 + g];
        s += (j < 6) ? b_cls[j] : b_box[j - 6];
        s_out[pos * 20 + j] = s;
    }
    __syncthreads();

    // write: score / prob(softmax over channel pairs (r, r+3)) / bbox
    if (tid < 96) {
        int pos = tid / 3, a = tid % 3;
        int w = w0 + pos;
        if (w < W) {
            int row   = rowBase + (h * W + w) * 3 + a;
            const float* so = s_out + pos * 20;
            int base2 = (b * ATOT + row) * 2;
            // score: channels (2a, 2a+1)
            out[base2 + 0] = so[2 * a + 0];
            out[base2 + 1] = so[2 * a + 1];
            // prob
            float* pout = out + (size_t)2 * NB * ATOT;
#pragma unroll
            for (int k = 0; k < 2; k++) {
                int c = 2 * a + k;
                int r = c % 3;
                float u = so[r], v = so[r + 3];
                float m  = fmaxf(u, v);
                float eu = __expf(u - m), ev = __expf(v - m);
                float num = (c < 3) ? eu : ev;
                pout[base2 + k] = num / (eu + ev);
            }
            // bbox: channels 4a..4a+3
            float* bout = out + (size_t)4 * NB * ATOT;
            int base4 = (b * ATOT + row) * 4;
#pragma unroll
            for (int j = 0; j < 4; j++) bout[base4 + j] = so[6 + 4 * a + j];
        }
    }
}

extern "C" void kernel_launch(void* const* d_in, const int* in_sizes, int n_in,
                              void* d_out, int out_size) {
    const float* feats[5];
    for (int i = 0; i < 5; i++) feats[i] = (const float*)d_in[i];
    // d_in[5] = im_info (unused by the reference computation)
    const float* W_conv = (const float*)d_in[6];
    const float* b_conv = (const float*)d_in[7];
    const float* W_cls  = (const float*)d_in[8];
    const float* b_cls  = (const float*)d_in[9];
    const float* W_box  = (const float*)d_in[10];
    const float* b_box  = (const float*)d_in[11];
    float* out = (float*)d_out;

    static const int HS[5] = {150, 75, 38, 19, 10};
    static const int WS[5] = {250, 125, 63, 32, 16};
    static const int RB[5] = {0, 112500, 140625, 147807, 149631};

    cudaFuncSetAttribute(rpn_level_kernel,
                         cudaFuncAttributeMaxDynamicSharedMemorySize, SMEM_BYTES);

    prep_weights<<<(DIN * NTAP * DMID + 255) / 256, 256>>>(W_conv);

    for (int l = 0; l < 5; l++) {
        dim3 grid((WS[l] + 31) / 32, HS[l], NB);
        rpn_level_kernel<<<grid, 256, SMEM_BYTES>>>(
            feats[l], b_conv, W_cls, b_cls, W_box, b_box, out,
            HS[l], WS[l], RB[l]);
    }
}

// round 5
// speedup vs baseline: 7.6359x; 7.6296x over previous
#include <cuda_runtime.h>
#include <cuda_fp16.h>

typedef unsigned int u32;

#define ATOT 150111
#define NB   4

// ---------------- static device scratch ----------------
static __device__ __align__(128) __half g_x[52859904];    // padded NHWC fp16 features (825936 rows x 64)
static __device__ __align__(128) __half g_wb[36*512*64];  // conv weights per k-block
static __device__ __align__(128) __half g_c1[226304*512]; // conv1 output (1768*128 pos x 512)

__constant__ int c_H[5]       = {150,75,38,19,10};
__constant__ int c_W[5]       = {250,125,63,32,16};
__constant__ int c_Wp[5]      = {252,127,65,34,18};
__constant__ int c_nt[5]      = {2,1,1,1,1};
__constant__ int c_plane[5]   = {38304,9779,2600,714,216};
__constant__ int c_xbase[5]   = {0,612864,769328,810928,822352};
__constant__ int c_tileEnd[5] = {1200,1500,1652,1728,1768};
__constant__ int c_rowBase[5] = {0,112500,140625,147807,149631};
// prep_x block decode
__constant__ int c_pbEnd[5]   = {19200,24000,25216,25520,25680};
__constant__ int c_wbl[5]     = {8,4,2,1,1};

__device__ __forceinline__ u32 smem_u32(const void* p){
    u32 a; asm("{ .reg .u64 t; cvta.to.shared.u64 t, %1; cvt.u32.u64 %0, t; }":"=r"(a):"l"(p));
    return a;
}
#define CP_ASYNC16(dst,src) asm volatile("cp.async.cg.shared.global [%0], [%1], 16;"::"r"(dst),"l"(src):"memory")
#define CP_COMMIT()     asm volatile("cp.async.commit_group;":::"memory")
#define CP_WAIT(n)      asm volatile("cp.async.wait_group %0;"::"n"(n):"memory")
#define LDSM_X4(r0,r1,r2,r3,a) asm volatile("ldmatrix.sync.aligned.m8n8.x4.shared.b16 {%0,%1,%2,%3}, [%4];" \
    : "=r"(r0),"=r"(r1),"=r"(r2),"=r"(r3) : "r"(a))
#define MMA16816(c0,c1,c2,c3,a0,a1,a2,a3,b0,b1) \
    asm volatile("mma.sync.aligned.m16n8k16.row.col.f32.f16.f16.f32 {%0,%1,%2,%3},{%4,%5,%6,%7},{%8,%9},{%0,%1,%2,%3};" \
    : "+f"(c0),"+f"(c1),"+f"(c2),"+f"(c3) : "r"(a0),"r"(a1),"r"(a2),"r"(a3),"r"(b0),"r"(b1))

// ---------------- prep kernels ----------------
__global__ void prep_zero() {
    size_t i = (size_t)blockIdx.x * blockDim.x + threadIdx.x;
    uint4* p = (uint4*)g_x;
    if (i < 52859904/8) p[i] = make_uint4(0,0,0,0);
}

__global__ void prep_w(const float* __restrict__ Wc){
    int idx = blockIdx.x*blockDim.x + threadIdx.x;
    if (idx >= 36*512*64) return;
    int j = idx & 63, o = (idx>>6)&511, kb = idx>>15;
    int cc = kb & 3, t = kb >> 2;
    g_wb[idx] = __float2half_rn(Wc[((size_t)o*256 + cc*64 + j)*9 + t]);
}

// smem-tiled NCHW fp32 -> padded NHWC fp16
__global__ __launch_bounds__(256)
void prep_x(const float* p0,const float* p1,const float* p2,const float* p3,const float* p4){
    __shared__ __half s[64][36];
    int bid = blockIdx.x, l = 0;
    while (bid >= c_pbEnd[l]) l++;
    int r = bid - (l ? c_pbEnd[l-1] : 0);
    int H = c_H[l], W = c_W[l], Wp = c_Wp[l], plane = c_plane[l];
    int wbl = c_wbl[l];
    int wb = r % wbl; int t1 = r / wbl;
    int h = t1 % H;   int bc = t1 / H;
    int b = bc >> 2, cc = bc & 3;
    const float* x = (l==0)?p0:(l==1)?p1:(l==2)?p2:(l==3)?p3:p4;

    int tid = threadIdx.x;
    {   // load 64ch x 32w, coalesced along w
        int c0 = tid >> 5, wl = tid & 31;
        int w = wb*32 + wl;
#pragma unroll
        for (int i = 0; i < 8; i++) {
            int ch = c0 + i*8;
            float v = (w < W) ? x[((size_t)(b*256 + cc*64 + ch)*H + h)*W + w] : 0.f;
            s[ch][wl] = __float2half_rn(v);
        }
    }
    __syncthreads();
    {   // store 32 rows x 128B, coalesced
        int cu = tid & 7, wl = tid >> 3;
        int w = wb*32 + wl;
        if (w < W) {
            size_t row = (size_t)c_xbase[l] + (size_t)(b*4 + cc)*plane + (size_t)(h+1)*Wp + (w+1);
            __half hv[8];
#pragma unroll
            for (int j = 0; j < 8; j++) hv[j] = s[cu*8 + j][wl];
            *(uint4*)((char*)g_x + row*128 + cu*16) = *(uint4*)hv;
        }
    }
}

// ---------------- gemm1: conv as implicit GEMM (HMMA) ----------------
#define STG_STRIDE 32768   // A 16KB + B 16KB per stage
#define SMEM_G1    98304   // 3 stages

__global__ void __launch_bounds__(256, 2)
gemm1(const float* __restrict__ b_conv)
{
    extern __shared__ char sm[];
    const u32 sb = smem_u32(sm);
    const int tid = threadIdx.x, lane = tid & 31, warp = tid >> 5;
    const int wm = warp & 1, wn = warp >> 1;
    const int n0 = blockIdx.x << 7;    // n-slice (fastest -> A tile L2-hot)
    const int tile = blockIdx.y;

    // decode tile -> (level, b, h, w0)
    int l = 0; while (tile >= c_tileEnd[l]) l++;
    int idx = tile - (l ? c_tileEnd[l-1] : 0);
    int nt = c_nt[l], H = c_H[l], Wp = c_Wp[l], plane = c_plane[l];
    (void)H;
    int perb = nt * c_H[l];
    int b = idx / perb; int rem = idx - b*perb;
    int h = rem / nt;   int w0 = (rem - h*nt) << 7;
    size_t rowb = (size_t)c_xbase[l] + (size_t)(b*4)*plane;

    // cp.async dst offsets (swizzled), shared by A and B tiles
    u32 dsw[4];
#pragma unroll
    for (int r = 0; r < 4; r++) {
        int u = tid + r*256, row = u >> 3, col = u & 7;
        dsw[r] = row*128 + (col ^ (row & 7))*16;
    }
    // ldmatrix offsets
    u32 offA[4], offB[4];
    {
        int rowA = wm*64 + (lane & 15), kA = lane >> 4;
        int rB0  = wn*32 + ((lane >> 4) << 3) + (lane & 7), kB = (lane >> 3) & 1;
#pragma unroll
        for (int ks = 0; ks < 4; ks++) {
            offA[ks] = rowA*128 + ((2*ks + kA) ^ (rowA & 7))*16;
            offB[ks] = rB0*128 + 16384 + ((2*ks + kB) ^ (lane & 7))*16;
        }
    }

    float c[4][4][4];
#pragma unroll
    for (int mf=0; mf<4; mf++)
#pragma unroll
        for (int nf=0; nf<4; nf++)
#pragma unroll
            for (int q=0; q<4; q++) c[mf][nf][q] = 0.f;

#define LOAD_STAGE(KB, SLOT) do {                                              \
        int _kb = (KB);                                                        \
        int _cc = _kb & 3, _t = _kb >> 2;                                      \
        int _ty = (_t >= 6) ? 2 : (_t >= 3) ? 1 : 0;                           \
        int _tx = _t - _ty*3;                                                  \
        const char* _gA = (const char*)g_x +                                   \
            (rowb + (size_t)_cc*plane + (size_t)(h+_ty)*Wp + (w0+_tx))*128;    \
        const char* _gB = (const char*)g_wb + ((size_t)_kb*512 + n0)*128;      \
        u32 _s = sb + (SLOT)*STG_STRIDE;                                       \
        _Pragma("unroll")                                                      \
        for (int _r = 0; _r < 4; _r++) {                                       \
            CP_ASYNC16(_s + dsw[_r],         _gA + tid*16 + _r*4096);          \
            CP_ASYNC16(_s + 16384 + dsw[_r], _gB + tid*16 + _r*4096);          \
        }                                                                      \
    } while (0)

    LOAD_STAGE(0, 0); CP_COMMIT();
    LOAD_STAGE(1, 1); CP_COMMIT();
    CP_WAIT(1);
    __syncthreads();

    for (int kb = 0; kb < 36; kb++) {
        if (kb + 2 < 36) LOAD_STAGE(kb + 2, (kb + 2) % 3);
        CP_COMMIT();

        u32 st = sb + (kb % 3)*STG_STRIDE;
#pragma unroll
        for (int ks = 0; ks < 4; ks++) {
            u32 a[4][4];
#pragma unroll
            for (int mf = 0; mf < 4; mf++)
                LDSM_X4(a[mf][0], a[mf][1], a[mf][2], a[mf][3],
                        st + mf*2048 + offA[ks]);
            u32 bf[4][2];
#pragma unroll
            for (int pr = 0; pr < 2; pr++)
                LDSM_X4(bf[2*pr][0], bf[2*pr][1], bf[2*pr+1][0], bf[2*pr+1][1],
                        st + pr*2048 + offB[ks]);
#pragma unroll
            for (int mf = 0; mf < 4; mf++)
#pragma unroll
                for (int nf = 0; nf < 4; nf++)
                    MMA16816(c[mf][nf][0], c[mf][nf][1], c[mf][nf][2], c[mf][nf][3],
                             a[mf][0], a[mf][1], a[mf][2], a[mf][3],
                             bf[nf][0], bf[nf][1]);
        }
        CP_WAIT(1);
        __syncthreads();
    }

    // epilogue: bias + relu -> fp16 conv1 scratch
    const int tileBase = tile << 7;
#pragma unroll
    for (int nf = 0; nf < 4; nf++) {
        int cn = n0 + wn*32 + nf*8 + (lane & 3)*2;
        float bx = b_conv[cn], by = b_conv[cn + 1];
#pragma unroll
        for (int mf = 0; mf < 4; mf++) {
            int row0 = wm*64 + mf*16 + (lane >> 2);
            float v0 = c[mf][nf][0] + bx, v1 = c[mf][nf][1] + by;
            float v2 = c[mf][nf][2] + bx, v3 = c[mf][nf][3] + by;
            v0 = v0 > 0.f ? v0 : 0.f;  v1 = v1 > 0.f ? v1 : 0.f;
            v2 = v2 > 0.f ? v2 : 0.f;  v3 = v3 > 0.f ? v3 : 0.f;
            __half2 h01 = __floats2half2_rn(v0, v1);
            __half2 h23 = __floats2half2_rn(v2, v3);
            *(u32*)(g_c1 + (size_t)(tileBase + row0)*512 + cn)     = *(u32*)&h01;
            *(u32*)(g_c1 + (size_t)(tileBase + row0 + 8)*512 + cn) = *(u32*)&h23;
        }
    }
}

// ---------------- head: 18x512 projection + softmax + scatter ----------------
__global__ __launch_bounds__(128)
void head(const float* __restrict__ W_cls, const float* __restrict__ b_cls,
          const float* __restrict__ W_box, const float* __restrict__ b_box,
          float* __restrict__ out)
{
    __shared__ float s_W[18*512];
    const int tid = threadIdx.x, tile = blockIdx.x;

    for (int i = tid; i < 18*512; i += 128) {
        int j = i >> 9, k = i & 511;
        s_W[i] = (j < 6) ? W_cls[j*512 + k] : W_box[(j-6)*512 + k];
    }
    __syncthreads();

    // decode tile
    int l = 0; while (tile >= c_tileEnd[l]) l++;
    int idx = tile - (l ? c_tileEnd[l-1] : 0);
    int nt = c_nt[l], H = c_H[l], W = c_W[l];
    int perb = nt * H;
    int b = idx / perb; int rem = idx - b*perb;
    int h = rem / nt;   int w0 = (rem - h*nt) << 7;

    const __half2* xr = (const __half2*)(g_c1 + ((size_t)tile*128 + tid)*512);
    float acc[18];
#pragma unroll
    for (int j = 0; j < 18; j++) acc[j] = 0.f;

    for (int k = 0; k < 512; k += 4) {
        float2 f01 = __half22float2(xr[k>>1]);
        float2 f23 = __half22float2(xr[(k>>1) + 1]);
#pragma unroll
        for (int j = 0; j < 18; j++) {
            float4 w4 = *(const float4*)(s_W + j*512 + k);
            acc[j] += f01.x*w4.x + f01.y*w4.y + f23.x*w4.z + f23.y*w4.w;
        }
    }

    int w = w0 + tid;
    if (w < W) {
        float so[18];
#pragma unroll
        for (int j = 0; j < 18; j++)
            so[j] = acc[j] + (j < 6 ? b_cls[j] : b_box[j-6]);
        int rowo = c_rowBase[l] + (h*W + w)*3;
        float* pout = out + (size_t)2*NB*ATOT;
        float* bout = out + (size_t)4*NB*ATOT;
#pragma unroll
        for (int a = 0; a < 3; a++) {
            int row = rowo + a;
            int base2 = (b*ATOT + row)*2;
            out[base2]   = so[2*a];
            out[base2+1] = so[2*a+1];
#pragma unroll
            for (int k = 0; k < 2; k++) {
                int c2 = 2*a + k, r = c2 % 3;
                float u0 = so[r], v0 = so[r+3];
                float m  = fmaxf(u0, v0);
                float eu = __expf(u0 - m), ev = __expf(v0 - m);
                pout[base2+k] = ((c2 < 3) ? eu : ev) / (eu + ev);
            }
            int base4 = (b*ATOT + row)*4;
#pragma unroll
            for (int j = 0; j < 4; j++) bout[base4+j] = so[6 + 4*a + j];
        }
    }
}

extern "C" void kernel_launch(void* const* d_in, const int* in_sizes, int n_in,
                              void* d_out, int out_size) {
    const float* f[5]; for (int i = 0; i < 5; i++) f[i] = (const float*)d_in[i];
    const float* W_conv = (const float*)d_in[6];
    const float* b_conv = (const float*)d_in[7];
    const float* W_cls  = (const float*)d_in[8];
    const float* b_cls  = (const float*)d_in[9];
    const float* W_box  = (const float*)d_in[10];
    const float* b_box  = (const float*)d_in[11];
    float* out = (float*)d_out;

    cudaFuncSetAttribute(gemm1, cudaFuncAttributeMaxDynamicSharedMemorySize, SMEM_G1);

    prep_zero<<<(52859904/8 + 255)/256, 256>>>();
    prep_x<<<25680, 256>>>(f[0], f[1], f[2], f[3], f[4]);
    prep_w<<<(36*512*64 + 255)/256, 256>>>(W_conv);
    gemm1<<<dim3(4, 1768), 256, SMEM_G1>>>(b_conv);
    head<<<1768, 128>>>(W_cls, b_cls, W_box, b_box, out);
}

// round 6
// speedup vs baseline: 9.4619x; 1.2391x over previous
#include <cuda_runtime.h>
#include <cuda_fp16.h>

typedef unsigned int u32;

#define ATOT 150111
#define NB   4

// ---------------- static device scratch ----------------
static __device__ __align__(128) __half g_x[52859904];    // padded NHWC fp16 features (825936 rows x 64)
static __device__ __align__(128) __half g_wb[36*512*64];  // conv weights per k-block
static __device__ __align__(128) __half g_c1[104595456];  // conv1 output (1596*128 pos x 512)

__constant__ int c_H[5]     = {150,75,38,19,10};
__constant__ int c_W[5]     = {250,125,63,32,16};
__constant__ int c_Wp[5]    = {252,127,65,34,18};
__constant__ int c_plane[5] = {38304,9779,2600,714,216};
__constant__ int c_xbase[5] = {0,612864,769328,810928,822352};
__constant__ int c_sEnd[5]  = {296,371,391,397,399};   // strip cum-ends per b
__constant__ int c_rowBase[5] = {0,112500,140625,147807,149631};
// prep_x block decode
__constant__ int c_pbEnd[5] = {19200,24000,25216,25520,25680};
__constant__ int c_wbl[5]   = {8,4,2,1,1};

#define NTILE 1596   // 4 b * 399 strips

__device__ __forceinline__ u32 smem_u32(const void* p){
    u32 a; asm("{ .reg .u64 t; cvta.to.shared.u64 t, %1; cvt.u32.u64 %0, t; }":"=r"(a):"l"(p));
    return a;
}
#define CP_ASYNC16(dst,src) asm volatile("cp.async.cg.shared.global [%0], [%1], 16;"::"r"(dst),"l"(src):"memory")
#define CP_COMMIT()     asm volatile("cp.async.commit_group;":::"memory")
#define CP_WAIT(n)      asm volatile("cp.async.wait_group %0;"::"n"(n):"memory")
#define LDSM_X4(r0,r1,r2,r3,a) asm volatile("ldmatrix.sync.aligned.m8n8.x4.shared.b16 {%0,%1,%2,%3}, [%4];" \
    : "=r"(r0),"=r"(r1),"=r"(r2),"=r"(r3) : "r"(a))
#define MMA16816(c0,c1,c2,c3,a0,a1,a2,a3,b0,b1) \
    asm volatile("mma.sync.aligned.m16n8k16.row.col.f32.f16.f16.f32 {%0,%1,%2,%3},{%4,%5,%6,%7},{%8,%9},{%0,%1,%2,%3};" \
    : "+f"(c0),"+f"(c1),"+f"(c2),"+f"(c3) : "r"(a0),"r"(a1),"r"(a2),"r"(a3),"r"(b0),"r"(b1))

// ---------------- prep kernels ----------------
__global__ void prep_zero() {
    size_t i = (size_t)blockIdx.x * blockDim.x + threadIdx.x;
    uint4* p = (uint4*)g_x;
    if (i < 52859904/8) p[i] = make_uint4(0,0,0,0);
}

__global__ void prep_w(const float* __restrict__ Wc){
    int idx = blockIdx.x*blockDim.x + threadIdx.x;
    if (idx >= 36*512*64) return;
    int j = idx & 63, o = (idx>>6)&511, kb = idx>>15;
    int cc = kb & 3, t = kb >> 2;
    g_wb[idx] = __float2half_rn(Wc[((size_t)o*256 + cc*64 + j)*9 + t]);
}

// smem-tiled NCHW fp32 -> padded NHWC fp16
__global__ __launch_bounds__(256)
void prep_x(const float* p0,const float* p1,const float* p2,const float* p3,const float* p4){
    __shared__ __half s[64][36];
    int bid = blockIdx.x, l = 0;
    while (bid >= c_pbEnd[l]) l++;
    int r = bid - (l ? c_pbEnd[l-1] : 0);
    int H = c_H[l], W = c_W[l], Wp = c_Wp[l], plane = c_plane[l];
    int wbl = c_wbl[l];
    int wb = r % wbl; int t1 = r / wbl;
    int h = t1 % H;   int bc = t1 / H;
    int b = bc >> 2, cc = bc & 3;
    const float* x = (l==0)?p0:(l==1)?p1:(l==2)?p2:(l==3)?p3:p4;

    int tid = threadIdx.x;
    {
        int c0 = tid >> 5, wl = tid & 31;
        int w = wb*32 + wl;
#pragma unroll
        for (int i = 0; i < 8; i++) {
            int ch = c0 + i*8;
            float v = (w < W) ? x[((size_t)(b*256 + cc*64 + ch)*H + h)*W + w] : 0.f;
            s[ch][wl] = __float2half_rn(v);
        }
    }
    __syncthreads();
    {
        int cu = tid & 7, wl = tid >> 3;
        int w = wb*32 + wl;
        if (w < W) {
            size_t row = (size_t)c_xbase[l] + (size_t)(b*4 + cc)*plane + (size_t)(h+1)*Wp + (w+1);
            __half hv[8];
#pragma unroll
            for (int j = 0; j < 8; j++) hv[j] = s[cu*8 + j][wl];
            *(uint4*)((char*)g_x + row*128 + cu*16) = *(uint4*)hv;
        }
    }
}

// ---------------- gemm1: conv as implicit GEMM (HMMA), strip tiling ----------------
#define STG_STRIDE 32768
#define SMEM_G1    98304

__global__ void __launch_bounds__(256, 2)
gemm1(const float* __restrict__ b_conv)
{
    extern __shared__ char sm[];
    const u32 sb = smem_u32(sm);
    const int tid = threadIdx.x, lane = tid & 31, warp = tid >> 5;
    const int wm = warp & 1, wn = warp >> 1;
    const int n0 = blockIdx.x << 7;
    const int tile = blockIdx.y;

    // strip decode
    int b = tile / 399; int r = tile - b*399;
    int l = 0; while (r >= c_sEnd[l]) l++;
    int s = r - (l ? c_sEnd[l-1] : 0);
    int Wp = c_Wp[l], plane = c_plane[l];
    size_t abase = (size_t)c_xbase[l] + (size_t)(b*4)*plane + (size_t)s*128;

    u32 dsw[4];
#pragma unroll
    for (int q = 0; q < 4; q++) {
        int u = tid + q*256, row = u >> 3, col = u & 7;
        dsw[q] = row*128 + (col ^ (row & 7))*16;
    }
    u32 offA[4], offB[4];
    {
        int rowA = wm*64 + (lane & 15), kA = lane >> 4;
        int rB0  = wn*32 + ((lane >> 4) << 3) + (lane & 7), kB = (lane >> 3) & 1;
#pragma unroll
        for (int ks = 0; ks < 4; ks++) {
            offA[ks] = rowA*128 + ((2*ks + kA) ^ (rowA & 7))*16;
            offB[ks] = rB0*128 + 16384 + ((2*ks + kB) ^ (lane & 7))*16;
        }
    }

    float c[4][4][4];
#pragma unroll
    for (int mf=0; mf<4; mf++)
#pragma unroll
        for (int nf=0; nf<4; nf++)
#pragma unroll
            for (int q=0; q<4; q++) c[mf][nf][q] = 0.f;

#define LOAD_STAGE(KB, SLOT) do {                                              \
        int _kb = (KB);                                                        \
        int _cc = _kb & 3, _t = _kb >> 2;                                      \
        int _ty = (_t >= 6) ? 2 : (_t >= 3) ? 1 : 0;                           \
        int _tx = _t - _ty*3;                                                  \
        const char* _gA = (const char*)g_x +                                   \
            (abase + (size_t)_cc*plane + _ty*Wp + _tx)*128;                    \
        const char* _gB = (const char*)g_wb + ((size_t)_kb*512 + n0)*128;      \
        u32 _s = sb + (SLOT)*STG_STRIDE;                                       \
        _Pragma("unroll")                                                      \
        for (int _r = 0; _r < 4; _r++) {                                       \
            CP_ASYNC16(_s + dsw[_r],         _gA + tid*16 + _r*4096);          \
            CP_ASYNC16(_s + 16384 + dsw[_r], _gB + tid*16 + _r*4096);          \
        }                                                                      \
    } while (0)

    LOAD_STAGE(0, 0); CP_COMMIT();
    LOAD_STAGE(1, 1); CP_COMMIT();
    CP_WAIT(1);
    __syncthreads();

    for (int kb = 0; kb < 36; kb++) {
        if (kb + 2 < 36) LOAD_STAGE(kb + 2, (kb + 2) % 3);
        CP_COMMIT();

        u32 st = sb + (kb % 3)*STG_STRIDE;
#pragma unroll
        for (int ks = 0; ks < 4; ks++) {
            u32 a[4][4];
#pragma unroll
            for (int mf = 0; mf < 4; mf++)
                LDSM_X4(a[mf][0], a[mf][1], a[mf][2], a[mf][3],
                        st + mf*2048 + offA[ks]);
            u32 bf[4][2];
#pragma unroll
            for (int pr = 0; pr < 2; pr++)
                LDSM_X4(bf[2*pr][0], bf[2*pr][1], bf[2*pr+1][0], bf[2*pr+1][1],
                        st + pr*2048 + offB[ks]);
#pragma unroll
            for (int mf = 0; mf < 4; mf++)
#pragma unroll
                for (int nf = 0; nf < 4; nf++)
                    MMA16816(c[mf][nf][0], c[mf][nf][1], c[mf][nf][2], c[mf][nf][3],
                             a[mf][0], a[mf][1], a[mf][2], a[mf][3],
                             bf[nf][0], bf[nf][1]);
        }
        CP_WAIT(1);
        __syncthreads();
    }

    const int tileBase = tile << 7;
#pragma unroll
    for (int nf = 0; nf < 4; nf++) {
        int cn = n0 + wn*32 + nf*8 + (lane & 3)*2;
        float bx = b_conv[cn], by = b_conv[cn + 1];
#pragma unroll
        for (int mf = 0; mf < 4; mf++) {
            int row0 = wm*64 + mf*16 + (lane >> 2);
            float v0 = c[mf][nf][0] + bx, v1 = c[mf][nf][1] + by;
            float v2 = c[mf][nf][2] + bx, v3 = c[mf][nf][3] + by;
            v0 = v0 > 0.f ? v0 : 0.f;  v1 = v1 > 0.f ? v1 : 0.f;
            v2 = v2 > 0.f ? v2 : 0.f;  v3 = v3 > 0.f ? v3 : 0.f;
            __half2 h01 = __floats2half2_rn(v0, v1);
            __half2 h23 = __floats2half2_rn(v2, v3);
            *(u32*)(g_c1 + (size_t)(tileBase + row0)*512 + cn)     = *(u32*)&h01;
            *(u32*)(g_c1 + (size_t)(tileBase + row0 + 8)*512 + cn) = *(u32*)&h23;
        }
    }
}

// ---------------- head: HMMA 18x512 projection + softmax + scatter ----------------
// smem: A stages 3 x 32KB = [0,98304) ; W fp16 [24][520] at 98304 (24960B)
// s_out[128][25] f32 reuses [0,12800) after the K loop.
#define SMEM_HD (98304 + 24960)

__global__ void __launch_bounds__(256, 1)
head(const float* __restrict__ W_cls, const float* __restrict__ b_cls,
     const float* __restrict__ W_box, const float* __restrict__ b_box,
     float* __restrict__ out)
{
    extern __shared__ char sm[];
    const u32 sb = smem_u32(sm);
    const int tid = threadIdx.x, lane = tid & 31, warp = tid >> 5;
    const int tile = blockIdx.x;

    // stage head weights: [n][520] fp16
    {
        __half* sW = (__half*)(sm + 98304);
        for (int i = tid; i < 24*512; i += 256) {
            int n = i >> 9, k = i & 511;
            float v = (n < 6) ? W_cls[n*512+k] : (n < 18) ? W_box[(n-6)*512+k] : 0.f;
            sW[n*520 + k] = __float2half_rn(v);
        }
    }

    // strip decode
    int b = tile / 399; int r = tile - b*399;
    int l = 0; while (r >= c_sEnd[l]) l++;
    int s = r - (l ? c_sEnd[l-1] : 0);
    int W = c_W[l], H = c_H[l], Wp = c_Wp[l];

    // cp.async offsets: per stage [kk=2][128 rows][128B swizzled]
    u32 dsw[8]; const char* srcs[8];
    {
        const char* gbase = (const char*)g_c1 + (size_t)tile*128*1024;
#pragma unroll
        for (int q = 0; q < 8; q++) {
            int u = tid + q*256;
            int kk = u >> 10, v = u & 1023, row = v >> 3, col = v & 7;
            dsw[q] = kk*16384 + row*128 + (col ^ (row & 7))*16;
            srcs[q] = gbase + (size_t)row*1024 + kk*128 + col*16;
        }
    }
    u32 offA[4];
    {
        int rowA = warp*16 + (lane & 15), kA = lane >> 4;
#pragma unroll
        for (int ks = 0; ks < 4; ks++)
            offA[ks] = rowA*128 + ((2*ks + kA) ^ (rowA & 7))*16;
    }
    const char* sWb = sm + 98304;
    const int nIdx = (lane >> 2);            // n within 8-group
    const int kLo  = (lane & 3) * 2;

    float c[3][4];
#pragma unroll
    for (int nf=0; nf<3; nf++)
#pragma unroll
        for (int q=0; q<4; q++) c[nf][q] = 0.f;

#define LOAD_HD(KC, SLOT) do {                                                 \
        u32 _s = sb + (SLOT)*32768;                                            \
        _Pragma("unroll")                                                      \
        for (int _q = 0; _q < 8; _q++)                                         \
            CP_ASYNC16(_s + dsw[_q], srcs[_q] + (KC)*256);                     \
    } while (0)

    LOAD_HD(0, 0); CP_COMMIT();
    LOAD_HD(1, 1); CP_COMMIT();
    CP_WAIT(1);
    __syncthreads();

    for (int kc = 0; kc < 4; kc++) {
        if (kc + 2 < 4) LOAD_HD(kc + 2, (kc + 2) % 3);
        CP_COMMIT();

        u32 st = sb + (kc % 3)*32768;
#pragma unroll
        for (int kk = 0; kk < 2; kk++)
#pragma unroll
            for (int ks = 0; ks < 4; ks++) {
                u32 a0,a1,a2,a3;
                LDSM_X4(a0,a1,a2,a3, st + kk*16384 + offA[ks]);
                int k0 = kc*128 + kk*64 + ks*16 + kLo;
#pragma unroll
                for (int nf = 0; nf < 3; nf++) {
                    int n = nf*8 + nIdx;
                    u32 b0 = *(const u32*)(sWb + (n*520 + k0)*2);
                    u32 b1 = *(const u32*)(sWb + (n*520 + k0 + 8)*2);
                    MMA16816(c[nf][0], c[nf][1], c[nf][2], c[nf][3],
                             a0, a1, a2, a3, b0, b1);
                }
            }
        CP_WAIT(1);
        __syncthreads();
    }

    // exchange through smem: s_out[128][25] f32
    float* s_out = (float*)sm;
    {
        int pos0 = warp*16 + (lane >> 2);
        int ncol = (lane & 3)*2;
#pragma unroll
        for (int nf = 0; nf < 3; nf++) {
            int n0c = nf*8 + ncol;
            s_out[pos0*25 + n0c]       = c[nf][0];
            s_out[pos0*25 + n0c + 1]   = c[nf][1];
            s_out[(pos0+8)*25 + n0c]   = c[nf][2];
            s_out[(pos0+8)*25 + n0c+1] = c[nf][3];
        }
    }
    __syncthreads();

    if (tid < 128) {
        int q = Wp + 1 + s*128 + tid;
        int hp = q / Wp, wp = q - hp*Wp;
        if (wp >= 1 && wp <= W && hp <= H) {
            int h = hp - 1, w = wp - 1;
            float so[18];
#pragma unroll
            for (int j = 0; j < 18; j++)
                so[j] = s_out[tid*25 + j] + (j < 6 ? b_cls[j] : b_box[j-6]);
            int rowo = c_rowBase[l] + (h*W + w)*3;
            float* pout = out + (size_t)2*NB*ATOT;
            float* bout = out + (size_t)4*NB*ATOT;
#pragma unroll
            for (int a = 0; a < 3; a++) {
                int row = rowo + a;
                int base2 = (b*ATOT + row)*2;
                out[base2]   = so[2*a];
                out[base2+1] = so[2*a+1];
#pragma unroll
                for (int k = 0; k < 2; k++) {
                    int c2 = 2*a + k, rr = c2 % 3;
                    float u0 = so[rr], v0 = so[rr+3];
                    float m  = fmaxf(u0, v0);
                    float eu = __expf(u0 - m), ev = __expf(v0 - m);
                    pout[base2+k] = ((c2 < 3) ? eu : ev) / (eu + ev);
                }
                int base4 = (b*ATOT + row)*4;
#pragma unroll
                for (int j = 0; j < 4; j++) bout[base4+j] = so[6 + 4*a + j];
            }
        }
    }
}

extern "C" void kernel_launch(void* const* d_in, const int* in_sizes, int n_in,
                              void* d_out, int out_size) {
    const float* f[5]; for (int i = 0; i < 5; i++) f[i] = (const float*)d_in[i];
    const float* W_conv = (const float*)d_in[6];
    const float* b_conv = (const float*)d_in[7];
    const float* W_cls  = (const float*)d_in[8];
    const float* b_cls  = (const float*)d_in[9];
    const float* W_box  = (const float*)d_in[10];
    const float* b_box  = (const float*)d_in[11];
    float* out = (float*)d_out;

    cudaFuncSetAttribute(gemm1, cudaFuncAttributeMaxDynamicSharedMemorySize, SMEM_G1);
    cudaFuncSetAttribute(head,  cudaFuncAttributeMaxDynamicSharedMemorySize, SMEM_HD);

    prep_zero<<<(52859904/8 + 255)/256, 256>>>();
    prep_x<<<25680, 256>>>(f[0], f[1], f[2], f[3], f[4]);
    prep_w<<<(36*512*64 + 255)/256, 256>>>(W_conv);
    gemm1<<<dim3(4, NTILE), 256, SMEM_G1>>>(b_conv);
    head<<<NTILE, 256, SMEM_HD>>>(W_cls, b_cls, W_box, b_box, out);
}

// round 7
// speedup vs baseline: 9.9997x; 1.0568x over previous
#include <cuda_runtime.h>
#include <cuda_fp16.h>

typedef unsigned int u32;

#define ATOT 150111
#define NB   4

// ---------------- static device scratch ----------------
static __device__ __align__(128) __half g_x[52859904];    // padded NHWC fp16 features (825936 rows x 64)
static __device__ __align__(128) __half g_wb[36*512*64];  // conv weights per k-block
static __device__ __align__(128) __half g_c1[104595456];  // conv1 output (1596*128 pos x 512)

__constant__ int c_H[5]     = {150,75,38,19,10};
__constant__ int c_W[5]     = {250,125,63,32,16};
__constant__ int c_Wp[5]    = {252,127,65,34,18};
__constant__ int c_plane[5] = {38304,9779,2600,714,216};
__constant__ int c_xbase[5] = {0,612864,769328,810928,822352};
__constant__ int c_sEnd[5]  = {296,371,391,397,399};   // strip cum-ends per b
__constant__ int c_rowBase[5] = {0,112500,140625,147807,149631};
// prep_x block decode
__constant__ int c_pbEnd[5] = {19200,24000,25216,25520,25680};
__constant__ int c_wbl[5]   = {8,4,2,1,1};

#define NTILE 1596   // 4 b * 399 strips

__device__ __forceinline__ u32 smem_u32(const void* p){
    u32 a; asm("{ .reg .u64 t; cvta.to.shared.u64 t, %1; cvt.u32.u64 %0, t; }":"=r"(a):"l"(p));
    return a;
}
#define CP_ASYNC16(dst,src) asm volatile("cp.async.cg.shared.global [%0], [%1], 16;"::"r"(dst),"l"(src):"memory")
#define CP_COMMIT()     asm volatile("cp.async.commit_group;":::"memory")
#define CP_WAIT(n)      asm volatile("cp.async.wait_group %0;"::"n"(n):"memory")
#define LDSM_X4(r0,r1,r2,r3,a) asm volatile("ldmatrix.sync.aligned.m8n8.x4.shared.b16 {%0,%1,%2,%3}, [%4];" \
    : "=r"(r0),"=r"(r1),"=r"(r2),"=r"(r3) : "r"(a))
#define MMA16816(c0,c1,c2,c3,a0,a1,a2,a3,b0,b1) \
    asm volatile("mma.sync.aligned.m16n8k16.row.col.f32.f16.f16.f32 {%0,%1,%2,%3},{%4,%5,%6,%7},{%8,%9},{%0,%1,%2,%3};" \
    : "+f"(c0),"+f"(c1),"+f"(c2),"+f"(c3) : "r"(a0),"r"(a1),"r"(a2),"r"(a3),"r"(b0),"r"(b1))

// ---------------- prep kernels ----------------
__global__ void prep_zero() {
    size_t i = (size_t)blockIdx.x * blockDim.x + threadIdx.x;
    uint4* p = (uint4*)g_x;
    if (i < 52859904/8) p[i] = make_uint4(0,0,0,0);
}

__global__ void prep_w(const float* __restrict__ Wc){
    int idx = blockIdx.x*blockDim.x + threadIdx.x;
    if (idx >= 36*512*64) return;
    int j = idx & 63, o = (idx>>6)&511, kb = idx>>15;
    int cc = kb & 3, t = kb >> 2;
    g_wb[idx] = __float2half_rn(Wc[((size_t)o*256 + cc*64 + j)*9 + t]);
}

// smem-tiled NCHW fp32 -> padded NHWC fp16
__global__ __launch_bounds__(256)
void prep_x(const float* p0,const float* p1,const float* p2,const float* p3,const float* p4){
    __shared__ __half s[64][36];
    int bid = blockIdx.x, l = 0;
    while (bid >= c_pbEnd[l]) l++;
    int r = bid - (l ? c_pbEnd[l-1] : 0);
    int H = c_H[l], W = c_W[l], Wp = c_Wp[l], plane = c_plane[l];
    int wbl = c_wbl[l];
    int wb = r % wbl; int t1 = r / wbl;
    int h = t1 % H;   int bc = t1 / H;
    int b = bc >> 2, cc = bc & 3;
    const float* x = (l==0)?p0:(l==1)?p1:(l==2)?p2:(l==3)?p3:p4;

    int tid = threadIdx.x;
    {
        int c0 = tid >> 5, wl = tid & 31;
        int w = wb*32 + wl;
#pragma unroll
        for (int i = 0; i < 8; i++) {
            int ch = c0 + i*8;
            float v = (w < W) ? x[((size_t)(b*256 + cc*64 + ch)*H + h)*W + w] : 0.f;
            s[ch][wl] = __float2half_rn(v);
        }
    }
    __syncthreads();
    {
        int cu = tid & 7, wl = tid >> 3;
        int w = wb*32 + wl;
        if (w < W) {
            size_t row = (size_t)c_xbase[l] + (size_t)(b*4 + cc)*plane + (size_t)(h+1)*Wp + (w+1);
            __half hv[8];
#pragma unroll
            for (int j = 0; j < 8; j++) hv[j] = s[cu*8 + j][wl];
            *(uint4*)((char*)g_x + row*128 + cu*16) = *(uint4*)hv;
        }
    }
}

// ---------------- gemm1: conv as implicit GEMM (HMMA), strip tiling ----------------
#define STG_STRIDE 32768
#define SMEM_G1    98304

__global__ void __launch_bounds__(256, 2)
gemm1(const float* __restrict__ b_conv)
{
    extern __shared__ char sm[];
    const u32 sb = smem_u32(sm);
    const int tid = threadIdx.x, lane = tid & 31, warp = tid >> 5;
    const int wm = warp & 1, wn = warp >> 1;
    const int n0 = blockIdx.x << 7;
    const int tile = blockIdx.y;

    // strip decode
    int b = tile / 399; int r = tile - b*399;
    int l = 0; while (r >= c_sEnd[l]) l++;
    int s = r - (l ? c_sEnd[l-1] : 0);
    int Wp = c_Wp[l], plane = c_plane[l];
    size_t abase = (size_t)c_xbase[l] + (size_t)(b*4)*plane + (size_t)s*128;

    u32 dsw[4];
#pragma unroll
    for (int q = 0; q < 4; q++) {
        int u = tid + q*256, row = u >> 3, col = u & 7;
        dsw[q] = row*128 + (col ^ (row & 7))*16;
    }
    u32 offA[4], offB[4];
    {
        int rowA = wm*64 + (lane & 15), kA = lane >> 4;
        int rB0  = wn*32 + ((lane >> 4) << 3) + (lane & 7), kB = (lane >> 3) & 1;
#pragma unroll
        for (int ks = 0; ks < 4; ks++) {
            offA[ks] = rowA*128 + ((2*ks + kA) ^ (rowA & 7))*16;
            offB[ks] = rB0*128 + 16384 + ((2*ks + kB) ^ (lane & 7))*16;
        }
    }

    float c[4][4][4];
#pragma unroll
    for (int mf=0; mf<4; mf++)
#pragma unroll
        for (int nf=0; nf<4; nf++)
#pragma unroll
            for (int q=0; q<4; q++) c[mf][nf][q] = 0.f;

#define GA_PTR(KB) ((const char*)g_x + (abase + (size_t)((KB) & 3)*plane +            \
        (size_t)((((KB)>>2) >= 6) ? 2 : (((KB)>>2) >= 3) ? 1 : 0)*Wp +                \
        (size_t)(((KB)>>2) - ((((KB)>>2) >= 6) ? 2 : (((KB)>>2) >= 3) ? 1 : 0)*3))*128)
#define GB_PTR(KB) ((const char*)g_wb + ((size_t)(KB)*512 + n0)*128)

#define LOAD_A(KB, SLOT) do {                                                  \
        const char* _gA = GA_PTR(KB);                                          \
        u32 _s = sb + (SLOT)*STG_STRIDE;                                       \
        _Pragma("unroll")                                                      \
        for (int _r = 0; _r < 4; _r++)                                         \
            CP_ASYNC16(_s + dsw[_r], _gA + tid*16 + _r*4096);                  \
    } while (0)
#define LOAD_B(KB, SLOT) do {                                                  \
        const char* _gB = GB_PTR(KB);                                          \
        u32 _s = sb + (SLOT)*STG_STRIDE + 16384;                               \
        _Pragma("unroll")                                                      \
        for (int _r = 0; _r < 4; _r++)                                         \
            CP_ASYNC16(_s + dsw[_r], _gB + tid*16 + _r*4096);                  \
    } while (0)

#define KS_STEP(ST, KS) do {                                                   \
        u32 a[4][4];                                                           \
        _Pragma("unroll")                                                      \
        for (int mf = 0; mf < 4; mf++)                                         \
            LDSM_X4(a[mf][0], a[mf][1], a[mf][2], a[mf][3],                    \
                    (ST) + mf*2048 + offA[KS]);                                \
        u32 bf[4][2];                                                          \
        _Pragma("unroll")                                                      \
        for (int pr = 0; pr < 2; pr++)                                         \
            LDSM_X4(bf[2*pr][0], bf[2*pr][1], bf[2*pr+1][0], bf[2*pr+1][1],    \
                    (ST) + pr*2048 + offB[KS]);                                \
        _Pragma("unroll")                                                      \
        for (int mf = 0; mf < 4; mf++)                                         \
            _Pragma("unroll")                                                  \
            for (int nf = 0; nf < 4; nf++)                                     \
                MMA16816(c[mf][nf][0], c[mf][nf][1], c[mf][nf][2], c[mf][nf][3],\
                         a[mf][0], a[mf][1], a[mf][2], a[mf][3],               \
                         bf[nf][0], bf[nf][1]);                                \
    } while (0)

    LOAD_A(0, 0); LOAD_B(0, 0); CP_COMMIT();
    LOAD_A(1, 1); LOAD_B(1, 1); CP_COMMIT();
    CP_WAIT(1);
    __syncthreads();

#pragma unroll 3
    for (int kb = 0; kb < 36; kb++) {
        const int slot = kb % 3;
        const int nslot = (kb + 2) % 3;
        u32 st = sb + slot*STG_STRIDE;

        KS_STEP(st, 0);
        if (kb + 2 < 36) LOAD_A(kb + 2, nslot);
        KS_STEP(st, 1);
        if (kb + 2 < 36) LOAD_B(kb + 2, nslot);
        CP_COMMIT();
        KS_STEP(st, 2);
        KS_STEP(st, 3);

        CP_WAIT(1);
        __syncthreads();
    }

    const int tileBase = tile << 7;
#pragma unroll
    for (int nf = 0; nf < 4; nf++) {
        int cn = n0 + wn*32 + nf*8 + (lane & 3)*2;
        float bx = b_conv[cn], by = b_conv[cn + 1];
#pragma unroll
        for (int mf = 0; mf < 4; mf++) {
            int row0 = wm*64 + mf*16 + (lane >> 2);
            float v0 = c[mf][nf][0] + bx, v1 = c[mf][nf][1] + by;
            float v2 = c[mf][nf][2] + bx, v3 = c[mf][nf][3] + by;
            v0 = v0 > 0.f ? v0 : 0.f;  v1 = v1 > 0.f ? v1 : 0.f;
            v2 = v2 > 0.f ? v2 : 0.f;  v3 = v3 > 0.f ? v3 : 0.f;
            __half2 h01 = __floats2half2_rn(v0, v1);
            __half2 h23 = __floats2half2_rn(v2, v3);
            *(u32*)(g_c1 + (size_t)(tileBase + row0)*512 + cn)     = *(u32*)&h01;
            *(u32*)(g_c1 + (size_t)(tileBase + row0 + 8)*512 + cn) = *(u32*)&h23;
        }
    }
}

// ---------------- head: HMMA 18x512 projection + softmax + scatter ----------------
#define SMEM_HD (98304 + 24960)

__global__ void __launch_bounds__(256, 1)
head(const float* __restrict__ W_cls, const float* __restrict__ b_cls,
     const float* __restrict__ W_box, const float* __restrict__ b_box,
     float* __restrict__ out)
{
    extern __shared__ char sm[];
    const u32 sb = smem_u32(sm);
    const int tid = threadIdx.x, lane = tid & 31, warp = tid >> 5;
    const int tile = blockIdx.x;

    {
        __half* sW = (__half*)(sm + 98304);
        for (int i = tid; i < 24*512; i += 256) {
            int n = i >> 9, k = i & 511;
            float v = (n < 6) ? W_cls[n*512+k] : (n < 18) ? W_box[(n-6)*512+k] : 0.f;
            sW[n*520 + k] = __float2half_rn(v);
        }
    }

    int b = tile / 399; int r = tile - b*399;
    int l = 0; while (r >= c_sEnd[l]) l++;
    int s = r - (l ? c_sEnd[l-1] : 0);
    int W = c_W[l], H = c_H[l], Wp = c_Wp[l];

    u32 dsw[8]; const char* srcs[8];
    {
        const char* gbase = (const char*)g_c1 + (size_t)tile*128*1024;
#pragma unroll
        for (int q = 0; q < 8; q++) {
            int u = tid + q*256;
            int kk = u >> 10, v = u & 1023, row = v >> 3, col = v & 7;
            dsw[q] = kk*16384 + row*128 + (col ^ (row & 7))*16;
            srcs[q] = gbase + (size_t)row*1024 + kk*128 + col*16;
        }
    }
    u32 offA[4];
    {
        int rowA = warp*16 + (lane & 15), kA = lane >> 4;
#pragma unroll
        for (int ks = 0; ks < 4; ks++)
            offA[ks] = rowA*128 + ((2*ks + kA) ^ (rowA & 7))*16;
    }
    const char* sWb = sm + 98304;
    const int nIdx = (lane >> 2);
    const int kLo  = (lane & 3) * 2;

    float c[3][4];
#pragma unroll
    for (int nf=0; nf<3; nf++)
#pragma unroll
        for (int q=0; q<4; q++) c[nf][q] = 0.f;

#define LOAD_HD(KC, SLOT) do {                                                 \
        u32 _s = sb + (SLOT)*32768;                                            \
        _Pragma("unroll")                                                      \
        for (int _q = 0; _q < 8; _q++)                                         \
            CP_ASYNC16(_s + dsw[_q], srcs[_q] + (KC)*256);                     \
    } while (0)

    LOAD_HD(0, 0); CP_COMMIT();
    LOAD_HD(1, 1); CP_COMMIT();
    CP_WAIT(1);
    __syncthreads();

    for (int kc = 0; kc < 4; kc++) {
        if (kc + 2 < 4) LOAD_HD(kc + 2, (kc + 2) % 3);
        CP_COMMIT();

        u32 st = sb + (kc % 3)*32768;
#pragma unroll
        for (int kk = 0; kk < 2; kk++)
#pragma unroll
            for (int ks = 0; ks < 4; ks++) {
                u32 a0,a1,a2,a3;
                LDSM_X4(a0,a1,a2,a3, st + kk*16384 + offA[ks]);
                int k0 = kc*128 + kk*64 + ks*16 + kLo;
#pragma unroll
                for (int nf = 0; nf < 3; nf++) {
                    int n = nf*8 + nIdx;
                    u32 b0 = *(const u32*)(sWb + (n*520 + k0)*2);
                    u32 b1 = *(const u32*)(sWb + (n*520 + k0 + 8)*2);
                    MMA16816(c[nf][0], c[nf][1], c[nf][2], c[nf][3],
                             a0, a1, a2, a3, b0, b1);
                }
            }
        CP_WAIT(1);
        __syncthreads();
    }

    float* s_out = (float*)sm;
    {
        int pos0 = warp*16 + (lane >> 2);
        int ncol = (lane & 3)*2;
#pragma unroll
        for (int nf = 0; nf < 3; nf++) {
            int n0c = nf*8 + ncol;
            s_out[pos0*25 + n0c]       = c[nf][0];
            s_out[pos0*25 + n0c + 1]   = c[nf][1];
            s_out[(pos0+8)*25 + n0c]   = c[nf][2];
            s_out[(pos0+8)*25 + n0c+1] = c[nf][3];
        }
    }
    __syncthreads();

    if (tid < 128) {
        int q = Wp + 1 + s*128 + tid;
        int hp = q / Wp, wp = q - hp*Wp;
        if (wp >= 1 && wp <= W && hp <= H) {
            int h = hp - 1, w = wp - 1;
            float so[18];
#pragma unroll
            for (int j = 0; j < 18; j++)
                so[j] = s_out[tid*25 + j] + (j < 6 ? b_cls[j] : b_box[j-6]);
            int rowo = c_rowBase[l] + (h*W + w)*3;
            float* pout = out + (size_t)2*NB*ATOT;
            float* bout = out + (size_t)4*NB*ATOT;
#pragma unroll
            for (int a = 0; a < 3; a++) {
                int row = rowo + a;
                int base2 = (b*ATOT + row)*2;
                out[base2]   = so[2*a];
                out[base2+1] = so[2*a+1];
#pragma unroll
                for (int k = 0; k < 2; k++) {
                    int c2 = 2*a + k, rr = c2 % 3;
                    float u0 = so[rr], v0 = so[rr+3];
                    float m  = fmaxf(u0, v0);
                    float eu = __expf(u0 - m), ev = __expf(v0 - m);
                    pout[base2+k] = ((c2 < 3) ? eu : ev) / (eu + ev);
                }
                int base4 = (b*ATOT + row)*4;
#pragma unroll
                for (int j = 0; j < 4; j++) bout[base4+j] = so[6 + 4*a + j];
            }
        }
    }
}

extern "C" void kernel_launch(void* const* d_in, const int* in_sizes, int n_in,
                              void* d_out, int out_size) {
    const float* f[5]; for (int i = 0; i < 5; i++) f[i] = (const float*)d_in[i];
    const float* W_conv = (const float*)d_in[6];
    const float* b_conv = (const float*)d_in[7];
    const float* W_cls  = (const float*)d_in[8];
    const float* b_cls  = (const float*)d_in[9];
    const float* W_box  = (const float*)d_in[10];
    const float* b_box  = (const float*)d_in[11];
    float* out = (float*)d_out;

    cudaFuncSetAttribute(gemm1, cudaFuncAttributeMaxDynamicSharedMemorySize, SMEM_G1);
    cudaFuncSetAttribute(head,  cudaFuncAttributeMaxDynamicSharedMemorySize, SMEM_HD);

    prep_zero<<<(52859904/8 + 255)/256, 256>>>();
    prep_x<<<25680, 256>>>(f[0], f[1], f[2], f[3], f[4]);
    prep_w<<<(36*512*64 + 255)/256, 256>>>(W_conv);
    gemm1<<<dim3(4, NTILE), 256, SMEM_G1>>>(b_conv);
    head<<<NTILE, 256, SMEM_HD>>>(W_cls, b_cls, W_box, b_box, out);
}

// round 8
// speedup vs baseline: 10.7788x; 1.0779x over previous
#include <cuda_runtime.h>
#include <cuda_fp16.h>

typedef unsigned int u32;

#define ATOT 150111
#define NB   4

// ---------------- static device scratch ----------------
static __device__ __align__(128) __half g_x[52859904];    // padded NHWC fp16 features (825936 rows x 64)
static __device__ __align__(128) __half g_wb[36*512*64];  // conv weights per k-block
static __device__ __align__(128) float  g_part[4*204288*18]; // head partials per n-slice

__constant__ int c_H[5]     = {150,75,38,19,10};
__constant__ int c_W[5]     = {250,125,63,32,16};
__constant__ int c_Wp[5]    = {252,127,65,34,18};
__constant__ int c_Hp[5]    = {152,77,40,21,12};
__constant__ int c_plane[5] = {38304,9779,2600,714,216};
__constant__ int c_xbase[5] = {0,612864,769328,810928,822352};
__constant__ int c_sEnd[5]  = {296,371,391,397,399};   // strip cum-ends per b
__constant__ int c_rowBase[5] = {0,112500,140625,147807,149631};
// prep_x block decode
__constant__ int c_pbEnd[5] = {19200,24000,25216,25520,25680};
__constant__ int c_wbl[5]   = {8,4,2,1,1};
// zero_pad decode: border rows per level (cum) and per-plane counts
__constant__ int c_bEnd[5]  = {12864,19328,22624,24320,25216};
__constant__ int c_bpp[5]   = {804,404,206,106,56};

#define NTILE 1596   // 4 b * 399 strips

__device__ __forceinline__ u32 smem_u32(const void* p){
    u32 a; asm("{ .reg .u64 t; cvta.to.shared.u64 t, %1; cvt.u32.u64 %0, t; }":"=r"(a):"l"(p));
    return a;
}
#define CP_ASYNC16(dst,src) asm volatile("cp.async.cg.shared.global [%0], [%1], 16;"::"r"(dst),"l"(src):"memory")
#define CP_COMMIT()     asm volatile("cp.async.commit_group;":::"memory")
#define CP_WAIT(n)      asm volatile("cp.async.wait_group %0;"::"n"(n):"memory")
#define LDSM_X4(r0,r1,r2,r3,a) asm volatile("ldmatrix.sync.aligned.m8n8.x4.shared.b16 {%0,%1,%2,%3}, [%4];" \
    : "=r"(r0),"=r"(r1),"=r"(r2),"=r"(r3) : "r"(a))
#define MMA16816(c0,c1,c2,c3,a0,a1,a2,a3,b0,b1) \
    asm volatile("mma.sync.aligned.m16n8k16.row.col.f32.f16.f16.f32 {%0,%1,%2,%3},{%4,%5,%6,%7},{%8,%9},{%0,%1,%2,%3};" \
    : "+f"(c0),"+f"(c1),"+f"(c2),"+f"(c3) : "r"(a0),"r"(a1),"r"(a2),"r"(a3),"r"(b0),"r"(b1))

// ---------------- prep kernels ----------------
// zero only border rows (h=0, h=Hp-1, w=0, w=W+1 per plane) + trailing slack
__global__ void zero_pad() {
    int id = blockIdx.x*blockDim.x + threadIdx.x;   // one per 16B
    if (id >= 25344*8) return;
    int bi = id >> 3, u = id & 7;
    size_t row;
    if (bi >= 25216) {
        row = 825808 + (bi - 25216);                // slack rows
    } else {
        int l = 0; while (bi >= c_bEnd[l]) l++;
        int r = bi - (l ? c_bEnd[l-1] : 0);
        int k = c_bpp[l];
        int plane = r / k, j = r - plane*k;
        int Wp = c_Wp[l], Hp = c_Hp[l], W = c_W[l];
        int hp, wp;
        if (j < 2*Wp) { hp = (j >= Wp) ? (Hp-1) : 0; wp = (j >= Wp) ? (j - Wp) : j; }
        else { int j2 = j - 2*Wp; hp = 1 + (j2 >> 1); wp = (j2 & 1) ? (W+1) : 0; }
        row = (size_t)c_xbase[l] + (size_t)plane*c_plane[l] + (size_t)hp*Wp + wp;
    }
    *(uint4*)((char*)g_x + row*128 + u*16) = make_uint4(0,0,0,0);
}

__global__ void prep_w(const float* __restrict__ Wc){
    int idx = blockIdx.x*blockDim.x + threadIdx.x;
    if (idx >= 36*512*64) return;
    int j = idx & 63, o = (idx>>6)&511, kb = idx>>15;
    int cc = kb & 3, t = kb >> 2;
    g_wb[idx] = __float2half_rn(Wc[((size_t)o*256 + cc*64 + j)*9 + t]);
}

// smem-tiled NCHW fp32 -> padded NHWC fp16 (interior rows only)
__global__ __launch_bounds__(256)
void prep_x(const float* p0,const float* p1,const float* p2,const float* p3,const float* p4){
    __shared__ __half s[64][36];
    int bid = blockIdx.x, l = 0;
    while (bid >= c_pbEnd[l]) l++;
    int r = bid - (l ? c_pbEnd[l-1] : 0);
    int H = c_H[l], W = c_W[l], Wp = c_Wp[l], plane = c_plane[l];
    int wbl = c_wbl[l];
    int wb = r % wbl; int t1 = r / wbl;
    int h = t1 % H;   int bc = t1 / H;
    int b = bc >> 2, cc = bc & 3;
    const float* x = (l==0)?p0:(l==1)?p1:(l==2)?p2:(l==3)?p3:p4;

    int tid = threadIdx.x;
    {
        int c0 = tid >> 5, wl = tid & 31;
        int w = wb*32 + wl;
#pragma unroll
        for (int i = 0; i < 8; i++) {
            int ch = c0 + i*8;
            float v = (w < W) ? x[((size_t)(b*256 + cc*64 + ch)*H + h)*W + w] : 0.f;
            s[ch][wl] = __float2half_rn(v);
        }
    }
    __syncthreads();
    {
        int cu = tid & 7, wl = tid >> 3;
        int w = wb*32 + wl;
        if (w < W) {
            size_t row = (size_t)c_xbase[l] + (size_t)(b*4 + cc)*plane + (size_t)(h+1)*Wp + (w+1);
            __half hv[8];
#pragma unroll
            for (int j = 0; j < 8; j++) hv[j] = s[cu*8 + j][wl];
            *(uint4*)((char*)g_x + row*128 + cu*16) = *(uint4*)hv;
        }
    }
}

// ---------------- gemm1: conv as implicit GEMM (HMMA) + fused head ----------------
#define STG_STRIDE 32768
#define SMEM_G1    (98304 + 6528)   // 3 stages + W_head [24][136] fp16

__global__ void __launch_bounds__(256, 2)
gemm1(const float* __restrict__ b_conv,
      const float* __restrict__ W_cls, const float* __restrict__ W_box)
{
    extern __shared__ char sm[];
    const u32 sb = smem_u32(sm);
    const int tid = threadIdx.x, lane = tid & 31, warp = tid >> 5;
    const int wm = warp & 1, wn = warp >> 1;
    const int n0 = blockIdx.x << 7;
    const int tile = blockIdx.y;

    // strip decode
    int b = tile / 399; int r = tile - b*399;
    int l = 0; while (r >= c_sEnd[l]) l++;
    int s = r - (l ? c_sEnd[l-1] : 0);
    int Wp = c_Wp[l], plane = c_plane[l];
    size_t abase = (size_t)c_xbase[l] + (size_t)(b*4)*plane + (size_t)s*128;

    // stage head-weight slice: sWh[24][136] fp16 (rows 18..23 zero)
    {
        __half* sWh = (__half*)(sm + 98304);
        for (int i = tid; i < 24*128; i += 256) {
            int j = i >> 7, k = i & 127;
            float v = (j < 6) ? W_cls[j*512 + n0 + k]
                    : (j < 18) ? W_box[(j-6)*512 + n0 + k] : 0.f;
            sWh[j*136 + k] = __float2half_rn(v);
        }
    }

    u32 dsw[4];
#pragma unroll
    for (int q = 0; q < 4; q++) {
        int u = tid + q*256, row = u >> 3, col = u & 7;
        dsw[q] = row*128 + (col ^ (row & 7))*16;
    }
    u32 offA[4], offB[4];
    {
        int rowA = wm*64 + (lane & 15), kA = lane >> 4;
        int rB0  = wn*32 + ((lane >> 4) << 3) + (lane & 7), kB = (lane >> 3) & 1;
#pragma unroll
        for (int ks = 0; ks < 4; ks++) {
            offA[ks] = rowA*128 + ((2*ks + kA) ^ (rowA & 7))*16;
            offB[ks] = rB0*128 + 16384 + ((2*ks + kB) ^ (lane & 7))*16;
        }
    }

    float c[4][4][4];
#pragma unroll
    for (int mf=0; mf<4; mf++)
#pragma unroll
        for (int nf=0; nf<4; nf++)
#pragma unroll
            for (int q=0; q<4; q++) c[mf][nf][q] = 0.f;

#define GA_PTR(KB) ((const char*)g_x + (abase + (size_t)((KB) & 3)*plane +            \
        (size_t)((((KB)>>2) >= 6) ? 2 : (((KB)>>2) >= 3) ? 1 : 0)*Wp +                \
        (size_t)(((KB)>>2) - ((((KB)>>2) >= 6) ? 2 : (((KB)>>2) >= 3) ? 1 : 0)*3))*128)
#define GB_PTR(KB) ((const char*)g_wb + ((size_t)(KB)*512 + n0)*128)

#define LOAD_A(KB, SLOT) do {                                                  \
        const char* _gA = GA_PTR(KB);                                          \
        u32 _s = sb + (SLOT)*STG_STRIDE;                                       \
        _Pragma("unroll")                                                      \
        for (int _r = 0; _r < 4; _r++)                                         \
            CP_ASYNC16(_s + dsw[_r], _gA + tid*16 + _r*4096);                  \
    } while (0)
#define LOAD_B(KB, SLOT) do {                                                  \
        const char* _gB = GB_PTR(KB);                                          \
        u32 _s = sb + (SLOT)*STG_STRIDE + 16384;                               \
        _Pragma("unroll")                                                      \
        for (int _r = 0; _r < 4; _r++)                                         \
            CP_ASYNC16(_s + dsw[_r], _gB + tid*16 + _r*4096);                  \
    } while (0)

#define KS_STEP(ST, KS) do {                                                   \
        u32 a[4][4];                                                           \
        _Pragma("unroll")                                                      \
        for (int mf = 0; mf < 4; mf++)                                         \
            LDSM_X4(a[mf][0], a[mf][1], a[mf][2], a[mf][3],                    \
                    (ST) + mf*2048 + offA[KS]);                                \
        u32 bf[4][2];                                                          \
        _Pragma("unroll")                                                      \
        for (int pr = 0; pr < 2; pr++)                                         \
            LDSM_X4(bf[2*pr][0], bf[2*pr][1], bf[2*pr+1][0], bf[2*pr+1][1],    \
                    (ST) + pr*2048 + offB[KS]);                                \
        _Pragma("unroll")                                                      \
        for (int mf = 0; mf < 4; mf++)                                         \
            _Pragma("unroll")                                                  \
            for (int nf = 0; nf < 4; nf++)                                     \
                MMA16816(c[mf][nf][0], c[mf][nf][1], c[mf][nf][2], c[mf][nf][3],\
                         a[mf][0], a[mf][1], a[mf][2], a[mf][3],               \
                         bf[nf][0], bf[nf][1]);                                \
    } while (0)

    LOAD_A(0, 0); LOAD_B(0, 0); CP_COMMIT();
    LOAD_A(1, 1); LOAD_B(1, 1); CP_COMMIT();
    CP_WAIT(1);
    __syncthreads();

#pragma unroll 3
    for (int kb = 0; kb < 36; kb++) {
        const int slot = kb % 3;
        const int nslot = (kb + 2) % 3;
        u32 st = sb + slot*STG_STRIDE;

        KS_STEP(st, 0);
        if (kb + 2 < 36) LOAD_A(kb + 2, nslot);
        KS_STEP(st, 1);
        if (kb + 2 < 36) LOAD_B(kb + 2, nslot);
        CP_COMMIT();
        KS_STEP(st, 2);
        KS_STEP(st, 3);

        CP_WAIT(1);
        __syncthreads();
    }

    // ---- fused epilogue: bias + ReLU -> fp16 tile in smem (slot 0, swizzled) ----
    // layout: row = (ch>=64)*128 + pos, 128B rows, chunk XOR (pos&7)
#pragma unroll
    for (int nf = 0; nf < 4; nf++) {
        int chl = wn*32 + nf*8 + (lane & 3)*2;      // 0..127
        int half = chl >> 6, chin = chl & 63;
        float bx = b_conv[n0 + chl], by = b_conv[n0 + chl + 1];
#pragma unroll
        for (int mf = 0; mf < 4; mf++) {
            int pos = wm*64 + mf*16 + (lane >> 2);
            float v0 = c[mf][nf][0] + bx, v1 = c[mf][nf][1] + by;
            float v2 = c[mf][nf][2] + bx, v3 = c[mf][nf][3] + by;
            v0 = v0 > 0.f ? v0 : 0.f;  v1 = v1 > 0.f ? v1 : 0.f;
            v2 = v2 > 0.f ? v2 : 0.f;  v3 = v3 > 0.f ? v3 : 0.f;
            __half2 h01 = __floats2half2_rn(v0, v1);
            __half2 h23 = __floats2half2_rn(v2, v3);
            u32 a0 = sb + (half*128 + pos)*128     + (((chin>>3) ^ (pos & 7)))*16     + (chin & 7)*2;
            u32 a1 = sb + (half*128 + pos + 8)*128 + (((chin>>3) ^ ((pos+8) & 7)))*16 + (chin & 7)*2;
            *(u32*)((char*)sm + (a0 - sb)) = *(u32*)&h01;
            *(u32*)((char*)sm + (a1 - sb)) = *(u32*)&h23;
        }
    }
    __syncthreads();

    // ---- head projection: per warp M=16, N=24, K=128 ----
    float c2[3][4];
#pragma unroll
    for (int nf=0; nf<3; nf++)
#pragma unroll
        for (int q=0; q<4; q++) c2[nf][q] = 0.f;

    const char* sWb = sm + 98304;
    {
        int rowA = warp*16 + (lane & 15), kA = lane >> 4;
        int nIdx = lane >> 2, kLo = (lane & 3)*2;
#pragma unroll
        for (int half = 0; half < 2; half++)
#pragma unroll
            for (int ks = 0; ks < 4; ks++) {
                u32 a0,a1,a2,a3;
                LDSM_X4(a0,a1,a2,a3,
                        sb + (half*128 + rowA)*128 + ((2*ks + kA) ^ (rowA & 7))*16);
                int k0 = half*64 + ks*16 + kLo;
#pragma unroll
                for (int nf = 0; nf < 3; nf++) {
                    int n = nf*8 + nIdx;
                    u32 b0 = *(const u32*)(sWb + (n*136 + k0)*2);
                    u32 b1 = *(const u32*)(sWb + (n*136 + k0 + 8)*2);
                    MMA16816(c2[nf][0], c2[nf][1], c2[nf][2], c2[nf][3],
                             a0, a1, a2, a3, b0, b1);
                }
            }
    }

    // ---- store 18-dim partials for this n-slice ----
    {
        float* gp = g_part + ((size_t)blockIdx.x*204288 + (size_t)tile*128)*18;
        int pos0 = warp*16 + (lane >> 2);
        int ncol = (lane & 3)*2;
#pragma unroll
        for (int nf = 0; nf < 3; nf++) {
            int n = nf*8 + ncol;
            if (n < 18) {
                gp[pos0*18 + n]     = c2[nf][0];
                gp[(pos0+8)*18 + n] = c2[nf][2];
            }
            if (n + 1 < 18) {
                gp[pos0*18 + n + 1]     = c2[nf][1];
                gp[(pos0+8)*18 + n + 1] = c2[nf][3];
            }
        }
    }
}

// ---------------- scatter: sum 4 slices + bias + softmax + write ----------------
__global__ __launch_bounds__(128)
void scatter(const float* __restrict__ b_cls, const float* __restrict__ b_box,
             float* __restrict__ out)
{
    const int tid = threadIdx.x, tile = blockIdx.x;

    int b = tile / 399; int r = tile - b*399;
    int l = 0; while (r >= c_sEnd[l]) l++;
    int s = r - (l ? c_sEnd[l-1] : 0);
    int W = c_W[l], H = c_H[l], Wp = c_Wp[l];

    int q = Wp + 1 + s*128 + tid;
    int hp = q / Wp, wp = q - hp*Wp;
    if (wp >= 1 && wp <= W && hp <= H) {
        int h = hp - 1, w = wp - 1;
        size_t pos = (size_t)tile*128 + tid;
        float so[18];
#pragma unroll
        for (int j = 0; j < 18; j++) {
            float v = g_part[pos*18 + j]
                    + g_part[204288u*18 + pos*18 + j]
                    + g_part[2u*204288*18 + pos*18 + j]
                    + g_part[3u*204288*18 + pos*18 + j];
            so[j] = v + (j < 6 ? b_cls[j] : b_box[j-6]);
        }
        int rowo = c_rowBase[l] + (h*W + w)*3;
        float* pout = out + (size_t)2*NB*ATOT;
        float* bout = out + (size_t)4*NB*ATOT;
#pragma unroll
        for (int a = 0; a < 3; a++) {
            int row = rowo + a;
            int base2 = (b*ATOT + row)*2;
            out[base2]   = so[2*a];
            out[base2+1] = so[2*a+1];
#pragma unroll
            for (int k = 0; k < 2; k++) {
                int c2 = 2*a + k, rr = c2 % 3;
                float u0 = so[rr], v0 = so[rr+3];
                float m  = fmaxf(u0, v0);
                float eu = __expf(u0 - m), ev = __expf(v0 - m);
                pout[base2+k] = ((c2 < 3) ? eu : ev) / (eu + ev);
            }
            int base4 = (b*ATOT + row)*4;
#pragma unroll
            for (int j = 0; j < 4; j++) bout[base4+j] = so[6 + 4*a + j];
        }
    }
}

extern "C" void kernel_launch(void* const* d_in, const int* in_sizes, int n_in,
                              void* d_out, int out_size) {
    const float* f[5]; for (int i = 0; i < 5; i++) f[i] = (const float*)d_in[i];
    const float* W_conv = (const float*)d_in[6];
    const float* b_conv = (const float*)d_in[7];
    const float* W_cls  = (const float*)d_in[8];
    const float* b_cls  = (const float*)d_in[9];
    const float* W_box  = (const float*)d_in[10];
    const float* b_box  = (const float*)d_in[11];
    float* out = (float*)d_out;

    cudaFuncSetAttribute(gemm1, cudaFuncAttributeMaxDynamicSharedMemorySize, SMEM_G1);

    zero_pad<<<(25344*8 + 255)/256, 256>>>();
    prep_x<<<25680, 256>>>(f[0], f[1], f[2], f[3], f[4]);
    prep_w<<<(36*512*64 + 255)/256, 256>>>(W_conv);
    gemm1<<<dim3(4, NTILE), 256, SMEM_G1>>>(b_conv, W_cls, W_box);
    scatter<<<NTILE, 128>>>(b_cls, b_box, out);
}